// round 1
// baseline (speedup 1.0000x reference)
#include <cuda_runtime.h>
#include <cuda_bf16.h>
#include <cstdint>

// Problem constants
#define BB 8
#define SS 2048
#define DD 512
#define II 2048

// Tiling
#define TILE_S 64          // s rows per CTA tile
#define TILE_I 128         // i cols per CTA
#define KC 32              // K chunk
#define NKT (DD / KC)      // 16 K chunks
#define NST (SS / TILE_S)  // 32 s tiles
#define SX 36              // padded smem stride for x/W tiles (float units)
#define SA 132             // padded smem stride for a/c scan tiles

// tf32-rounded scratch copies of inputs
__device__ float g_x[(size_t)BB * SS * DD];
__device__ float g_wa[(size_t)II * DD];
__device__ float g_wi[(size_t)II * DD];

__device__ __forceinline__ float ex2f_(float x) {
    float y; asm("ex2.approx.f32 %0, %1;" : "=f"(y) : "f"(x)); return y;
}
__device__ __forceinline__ float rcpf_(float x) {
    float y; asm("rcp.approx.f32 %0, %1;" : "=f"(y) : "f"(x)); return y;
}
__device__ __forceinline__ float sqrtf_(float x) {
    float y; asm("sqrt.approx.f32 %0, %1;" : "=f"(y) : "f"(x)); return y;
}
__device__ __forceinline__ float sigmoidf_(float x) {
    // 1/(1+2^(-x*log2 e))
    return rcpf_(1.0f + ex2f_(-1.44269504f * x));
}
__device__ __forceinline__ float cvt_tf32(float x) {
    float y; asm("cvt.rna.tf32.f32 %0, %1;" : "=f"(y) : "f"(x)); return y;
}

__device__ __forceinline__ void cp16(uint32_t dst, const float* src) {
    asm volatile("cp.async.cg.shared.global [%0], [%1], 16;\n" :: "r"(dst), "l"(src));
}

__device__ __forceinline__ void mma_tf32(float* c, const float* a, float b0, float b1) {
    asm volatile(
        "mma.sync.aligned.m16n8k8.row.col.f32.tf32.tf32.f32 "
        "{%0,%1,%2,%3}, {%4,%5,%6,%7}, {%8,%9}, {%0,%1,%2,%3};\n"
        : "+f"(c[0]), "+f"(c[1]), "+f"(c[2]), "+f"(c[3])
        : "r"(__float_as_uint(a[0])), "r"(__float_as_uint(a[1])),
          "r"(__float_as_uint(a[2])), "r"(__float_as_uint(a[3])),
          "r"(__float_as_uint(b0)), "r"(__float_as_uint(b1)));
}

// Prepass: round x, Wa, Wi to tf32 (rna) into device scratch
__global__ void prepass_kernel(const float* __restrict__ x,
                               const float* __restrict__ wa,
                               const float* __restrict__ wi) {
    int i = blockIdx.x * blockDim.x + threadIdx.x;  // grid exactly covers x
    g_x[i] = cvt_tf32(x[i]);
    if (i < II * DD) {
        g_wa[i] = cvt_tf32(wa[i]);
        g_wi[i] = cvt_tf32(wi[i]);
    }
}

// smem layout (floats):
//  xs  : 2 * 64 * SX
//  was : 2 * 128 * SX
//  wis : 2 * 128 * SX
//  a_s : 64 * SA
//  c_s : 64 * SA
#define SMEM_FLOATS (2*TILE_S*SX + 2*TILE_I*SX + 2*TILE_I*SX + 2*TILE_S*SA)
#define SMEM_BYTES  (SMEM_FLOATS * 4)

__global__ __launch_bounds__(256, 1)
void fused_gru_kernel(const float* __restrict__ ba,
                      const float* __restrict__ bi,
                      const float* __restrict__ gate,
                      float* __restrict__ out) {
    extern __shared__ float sm[];
    float* xs  = sm;                       // [2][64][SX]
    float* was = xs  + 2 * TILE_S * SX;    // [2][128][SX]
    float* wis = was + 2 * TILE_I * SX;    // [2][128][SX]
    float* a_s = wis + 2 * TILE_I * SX;    // [64][SA]
    float* c_s = a_s + TILE_S * SA;        // [64][SA]

    const int tid  = threadIdx.x;
    const int lane = tid & 31;
    const int w    = tid >> 5;       // 0..7
    const int wm   = w >> 2;         // 0..1 : s-offset wm*32
    const int wn   = w & 3;          // 0..3 : i-offset wn*32
    const int g    = lane >> 2;      // 0..7
    const int tg   = lane & 3;       // 0..3

    const int b  = blockIdx.x >> 4;
    const int it = blockIdx.x & 15;
    const int i0 = it * TILE_I;

    // Per-thread column constants: 4 ntiles x 2 (frag col parity)
    float alpr[4][2], bar[4][2], bir[4][2];
#pragma unroll
    for (int nt = 0; nt < 4; ++nt) {
#pragma unroll
        for (int j = 0; j < 2; ++j) {
            int ii = i0 + wn * 32 + nt * 8 + tg * 2 + j;
            alpr[nt][j] = sigmoidf_(gate[ii]);
            bar[nt][j]  = ba[ii];
            bir[nt][j]  = bi[ii];
        }
    }

    const float* xg  = g_x  + (size_t)b * SS * DD;
    const float* wag = g_wa + (size_t)i0 * DD;
    const float* wig = g_wi + (size_t)i0 * DD;

    uint32_t xs_u  = (uint32_t)__cvta_generic_to_shared(xs);
    uint32_t was_u = (uint32_t)__cvta_generic_to_shared(was);
    uint32_t wis_u = (uint32_t)__cvta_generic_to_shared(wis);

    float h = 0.0f;  // scan state (tid < 128)

    for (int st = 0; st < NST; ++st) {
        const int s0 = st * TILE_S;

        float acc[2][2][4][4];  // [gemm][mtile][ntile][frag]
#pragma unroll
        for (int gm = 0; gm < 2; ++gm)
#pragma unroll
            for (int mt = 0; mt < 2; ++mt)
#pragma unroll
                for (int nt = 0; nt < 4; ++nt)
#pragma unroll
                    for (int f = 0; f < 4; ++f) acc[gm][mt][nt][f] = 0.0f;

        // ---- prefetch chunk 0 into stage 0 ----
        {
            const int kt = 0, stg = 0;
#pragma unroll
            for (int j = 0; j < 2; ++j) {  // x: 512 float4
                int idx = tid + j * 256;
                int r = idx >> 3, c4 = idx & 7;
                cp16(xs_u + (stg * TILE_S * SX + r * SX + c4 * 4) * 4,
                     xg + (size_t)(s0 + r) * DD + kt * KC + c4 * 4);
            }
#pragma unroll
            for (int j = 0; j < 4; ++j) {  // W: 1024 float4 each
                int idx = tid + j * 256;
                int r = idx >> 3, c4 = idx & 7;
                size_t go = (size_t)r * DD + kt * KC + c4 * 4;
                uint32_t so = (stg * TILE_I * SX + r * SX + c4 * 4) * 4;
                cp16(was_u + so, wag + go);
                cp16(wis_u + so, wig + go);
            }
            asm volatile("cp.async.commit_group;\n");
        }

        // ---- K loop ----
        for (int kt = 0; kt < NKT; ++kt) {
            __syncthreads();  // prior stage fully consumed before refill
            if (kt + 1 < NKT) {
                const int stg = (kt + 1) & 1;
#pragma unroll
                for (int j = 0; j < 2; ++j) {
                    int idx = tid + j * 256;
                    int r = idx >> 3, c4 = idx & 7;
                    cp16(xs_u + (stg * TILE_S * SX + r * SX + c4 * 4) * 4,
                         xg + (size_t)(s0 + r) * DD + (kt + 1) * KC + c4 * 4);
                }
#pragma unroll
                for (int j = 0; j < 4; ++j) {
                    int idx = tid + j * 256;
                    int r = idx >> 3, c4 = idx & 7;
                    size_t go = (size_t)r * DD + (kt + 1) * KC + c4 * 4;
                    uint32_t so = (stg * TILE_I * SX + r * SX + c4 * 4) * 4;
                    cp16(was_u + so, wag + go);
                    cp16(wis_u + so, wig + go);
                }
                asm volatile("cp.async.commit_group;\n");
                asm volatile("cp.async.wait_group 1;\n");
            } else {
                asm volatile("cp.async.wait_group 0;\n");
            }
            __syncthreads();  // loaded data visible to all

            const int stg = kt & 1;
            const float* xst = xs  + stg * TILE_S * SX;
            const float* wat = was + stg * TILE_I * SX;
            const float* wit = wis + stg * TILE_I * SX;

#pragma unroll
            for (int k8 = 0; k8 < KC / 8; ++k8) {
                const int kb = k8 * 8;
                float afr[2][4];
#pragma unroll
                for (int mt = 0; mt < 2; ++mt) {
                    int r = wm * 32 + mt * 16;
                    afr[mt][0] = xst[(r + g) * SX + kb + tg];
                    afr[mt][1] = xst[(r + 8 + g) * SX + kb + tg];
                    afr[mt][2] = xst[(r + g) * SX + kb + tg + 4];
                    afr[mt][3] = xst[(r + 8 + g) * SX + kb + tg + 4];
                }
#pragma unroll
                for (int nt = 0; nt < 4; ++nt) {
                    int c = wn * 32 + nt * 8;
                    float b0a = wat[(c + g) * SX + kb + tg];
                    float b1a = wat[(c + g) * SX + kb + tg + 4];
                    float b0i = wit[(c + g) * SX + kb + tg];
                    float b1i = wit[(c + g) * SX + kb + tg + 4];
#pragma unroll
                    for (int mt = 0; mt < 2; ++mt) {
                        mma_tf32(acc[0][mt][nt], afr[mt], b0a, b1a);
                        mma_tf32(acc[1][mt][nt], afr[mt], b0i, b1i);
                    }
                }
            }
        }

        // ---- elementwise epilogue: regs -> a_s/c_s ----
#pragma unroll
        for (int mt = 0; mt < 2; ++mt) {
#pragma unroll
            for (int nt = 0; nt < 4; ++nt) {
#pragma unroll
                for (int f = 0; f < 4; ++f) {
                    int r   = wm * 32 + mt * 16 + g + ((f >= 2) ? 8 : 0);
                    int col = wn * 32 + nt * 8 + tg * 2 + (f & 1);
                    float pa = acc[0][mt][nt][f] + bar[nt][f & 1];
                    float pi = acc[1][mt][nt][f] + bir[nt][f & 1];
                    float rg = sigmoidf_(pa);
                    float ig = sigmoidf_(pi);
                    float ad = alpr[nt][f & 1] * ex2f_(-1.5849625007f * rg);
                    float dr = sqrtf_(fmaxf(1.0f - ad * ad, 0.0f)) * (ig * pi);
                    a_s[r * SA + col] = ad;
                    c_s[r * SA + col] = dr;
                }
            }
        }
        __syncthreads();

        // ---- sequential scan over this s-tile ----
        if (tid < TILE_I) {
            float* op = out + ((size_t)b * SS + s0) * II + i0 + tid;
#pragma unroll 4
            for (int s = 0; s < TILE_S; ++s) {
                h = fmaf(a_s[s * SA + tid], h, c_s[s * SA + tid]);
                *op = h;
                op += II;
            }
        }
        __syncthreads();
    }
}

extern "C" void kernel_launch(void* const* d_in, const int* in_sizes, int n_in,
                              void* d_out, int out_size) {
    const float* x    = (const float*)d_in[0];
    const float* Wa   = (const float*)d_in[1];
    const float* ba   = (const float*)d_in[2];
    const float* Wi   = (const float*)d_in[3];
    const float* bi   = (const float*)d_in[4];
    const float* gate = (const float*)d_in[5];
    float* out = (float*)d_out;

    // tf32 rounding prepass (x dominates: 8*2048*512 = 8388608 elems)
    prepass_kernel<<<(BB * SS * DD) / 256, 256>>>(x, Wa, Wi);

    cudaFuncSetAttribute(fused_gru_kernel,
                         cudaFuncAttributeMaxDynamicSharedMemorySize, SMEM_BYTES);
    fused_gru_kernel<<<BB * (II / TILE_I), 256, SMEM_BYTES>>>(ba, bi, gate, out);
}